// round 1
// baseline (speedup 1.0000x reference)
#include <cuda_runtime.h>

#define NLOC  384
#define DHID  32
#define DPAIR 64
#define NCOL  (NLOC * DPAIR)   // 24576

// ---------------- scratch (static device globals; no allocations) ----------
__device__ float g_At[DHID * NLOC];   // a transposed: [32][384]
__device__ float g_B [NLOC * DHID];   // b:            [384][32]
__device__ float g_C [DHID * NCOL];   // C[x][j*64+p]: [32][24576]  (3 MB)

// ---------------- f32x2 helpers (Blackwell packed fp32) --------------------
__device__ __forceinline__ unsigned long long dup2(float v) {
    unsigned long long r;
    asm("mov.b64 %0, {%1, %1};" : "=l"(r) : "f"(v));
    return r;
}
__device__ __forceinline__ void fma2(unsigned long long& d,
                                     unsigned long long a,
                                     unsigned long long b) {
    asm("fma.rn.f32x2 %0, %1, %2, %0;" : "+l"(d) : "l"(a), "l"(b));
}
__device__ __forceinline__ float2 unpk(unsigned long long u) {
    float2 r;
    asm("mov.b64 {%0, %1}, %2;" : "=f"(r.x), "=f"(r.y) : "l"(u));
    return r;
}

// ---------------- kernel 1: ab = m @ W_in^T + b_in, * op_mask --------------
// grid 96 x 256 threads; block handles 4 rows of m.
__global__ __launch_bounds__(256) void k1_proj(
        const float* __restrict__ m,
        const float* __restrict__ W_in,
        const float* __restrict__ b_in,
        const float* __restrict__ op_mask)
{
    __shared__ float W_s[64 * 129];   // padded rows -> conflict-free
    __shared__ float m_s[4 * 128];
    const int tid = threadIdx.x;
    const int n0  = blockIdx.x * 4;

    #pragma unroll
    for (int i = 0; i < 32; ++i) {
        int e = tid + i * 256;              // 0..8191
        int h = e >> 7, k = e & 127;
        W_s[h * 129 + k] = W_in[e];         // W_in is [64][128] row-major
    }
    #pragma unroll
    for (int i = 0; i < 2; ++i) {
        int e = tid + i * 256;              // 0..511
        m_s[e] = m[n0 * 128 + e];
    }
    __syncthreads();

    const int nl = tid >> 6;                // 0..3
    const int h  = tid & 63;                // 0..63
    float acc = b_in[h];
    #pragma unroll 16
    for (int k = 0; k < 128; ++k)
        acc += m_s[nl * 128 + k] * W_s[h * 129 + k];
    acc *= op_mask[0];

    const int n = n0 + nl;
    if (h < DHID) g_At[h * NLOC + n]        = acc;   // a, transposed
    else          g_B [n * DHID + (h - DHID)] = acc; // b
}

// ---------------- kernel 2: C[x][j*64+p] = sum_y b[j,y]*W_out[p,32x+y] -----
// grid (32 x-slices, 6 j-tiles of 64) x 256 threads, 4x4 register tile.
__global__ __launch_bounds__(256) void k2_makeC(const float* __restrict__ W_out)
{
    __shared__ float W_sT[32 * 68];   // [y][p], padded stride 68
    __shared__ float b_sT[32 * 68];   // [y][j], padded stride 68
    const int tid = threadIdx.x;
    const int x   = blockIdx.x;           // 0..31
    const int j0  = blockIdx.y * 64;      // 0..320

    #pragma unroll
    for (int i = 0; i < 8; ++i) {
        int e = tid + i * 256;             // 0..2047
        int p = e >> 5, y = e & 31;        // p doubles as local j index
        W_sT[y * 68 + p] = W_out[p * 1024 + x * 32 + y];
        b_sT[y * 68 + p] = g_B[(j0 + p) * DHID + y];
    }
    __syncthreads();

    const int jl = (tid >> 4) * 4;
    const int pl = (tid & 15) * 4;
    float acc[4][4] = {};
    #pragma unroll
    for (int y = 0; y < 32; ++y) {
        float4 bq = *(const float4*)&b_sT[y * 68 + jl];
        float4 wq = *(const float4*)&W_sT[y * 68 + pl];
        const float* bb = &bq.x;
        const float* ww = &wq.x;
        #pragma unroll
        for (int r = 0; r < 4; ++r)
            #pragma unroll
            for (int c = 0; c < 4; ++c)
                acc[r][c] += bb[r] * ww[c];
    }
    #pragma unroll
    for (int r = 0; r < 4; ++r) {
        float4 o = make_float4(acc[r][0], acc[r][1], acc[r][2], acc[r][3]);
        *(float4*)&g_C[x * NCOL + (j0 + jl + r) * 64 + pl] = o;
    }
}

// ---------------- kernel 3: Z[i,n] = sum_x a[i,x] * C[x,n] -----------------
// GEMM M=384, N=24576, K=32. BM=BN=128, 256 threads, 8x8 per thread,
// packed f32x2 accumulation (a duplicated in smem).
__global__ __launch_bounds__(256) void k3_gemm(
        const float* __restrict__ b_out,
        const float* __restrict__ op_norm,
        float* __restrict__ out)
{
    __shared__ unsigned long long a_s[32 * 128];  // [k][m], dup'd pairs (32 KB)
    __shared__ float              c_s[32 * 128];  // [k][n]               (16 KB)
    const int tid = threadIdx.x;
    const int n0  = blockIdx.x * 128;
    const int m0  = blockIdx.y * 128;

    #pragma unroll
    for (int i = 0; i < 16; ++i) {
        int e = tid + i * 256;              // 0..4095
        int k = e >> 7, mm = e & 127;       // mm fast -> conflict-free smem writes
        a_s[k * 128 + mm] = dup2(g_At[k * NLOC + m0 + mm]);  // coalesced (At)
        c_s[k * 128 + mm] = g_C [k * NCOL + n0 + mm];        // coalesced
    }
    __syncthreads();

    const int tm = (tid >> 4) * 8;          // 0..120
    const int tn = (tid & 15) * 8;          // 0..120
    unsigned long long acc[8][4];
    #pragma unroll
    for (int mi = 0; mi < 8; ++mi)
        #pragma unroll
        for (int q = 0; q < 4; ++q)
            acc[mi][q] = 0ULL;              // bits of (0.f, 0.f)

    #pragma unroll 4
    for (int k = 0; k < 32; ++k) {
        const unsigned long long* ap = &a_s[k * 128 + tm];
        ulonglong2 a01 = *(const ulonglong2*)(ap);
        ulonglong2 a23 = *(const ulonglong2*)(ap + 2);
        ulonglong2 a45 = *(const ulonglong2*)(ap + 4);
        ulonglong2 a67 = *(const ulonglong2*)(ap + 6);
        const float* cp = &c_s[k * 128 + tn];
        ulonglong2 b01 = *(const ulonglong2*)(cp);       // (c[n],c[n+1]),(c[n+2],c[n+3])
        ulonglong2 b23 = *(const ulonglong2*)(cp + 4);

        unsigned long long av[8] = {a01.x, a01.y, a23.x, a23.y,
                                    a45.x, a45.y, a67.x, a67.y};
        unsigned long long bv[4] = {b01.x, b01.y, b23.x, b23.y};
        #pragma unroll
        for (int mi = 0; mi < 8; ++mi)
            #pragma unroll
            for (int q = 0; q < 4; ++q)
                fma2(acc[mi][q], av[mi], bv[q]);
    }

    const float opn = op_norm[0];
    float bo[8];
    #pragma unroll
    for (int l = 0; l < 8; ++l) bo[l] = b_out[(tn + l) & 63];  // n0%64==0

    #pragma unroll
    for (int mi = 0; mi < 8; ++mi) {
        float2 t0 = unpk(acc[mi][0]);
        float2 t1 = unpk(acc[mi][1]);
        float2 t2 = unpk(acc[mi][2]);
        float2 t3 = unpk(acc[mi][3]);
        float4 r0 = make_float4((t0.x + bo[0]) * opn, (t0.y + bo[1]) * opn,
                                (t1.x + bo[2]) * opn, (t1.y + bo[3]) * opn);
        float4 r1 = make_float4((t2.x + bo[4]) * opn, (t2.y + bo[5]) * opn,
                                (t3.x + bo[6]) * opn, (t3.y + bo[7]) * opn);
        int row = (m0 + tm + mi) * NCOL + n0 + tn;
        *(float4*)&out[row]     = r0;
        *(float4*)&out[row + 4] = r1;
    }
}

// ---------------- launch ---------------------------------------------------
extern "C" void kernel_launch(void* const* d_in, const int* in_sizes, int n_in,
                              void* d_out, int out_size)
{
    (void)in_sizes; (void)n_in; (void)out_size;
    const float* m       = (const float*)d_in[0];
    /* d_in[1] = nlist: unused by the reference */
    const float* op_mask = (const float*)d_in[2];
    const float* op_norm = (const float*)d_in[3];
    const float* W_in    = (const float*)d_in[4];
    const float* b_in    = (const float*)d_in[5];
    const float* W_out   = (const float*)d_in[6];
    const float* b_out   = (const float*)d_in[7];
    float* out = (float*)d_out;

    k1_proj <<<96, 256>>>(m, W_in, b_in, op_mask);
    k2_makeC<<<dim3(32, 6), 256>>>(W_out);
    k3_gemm <<<dim3(192, 3), 256>>>(b_out, op_norm, out);
}

// round 2
// speedup vs baseline: 1.0558x; 1.0558x over previous
#include <cuda_runtime.h>

#define NLOC  384
#define DHID  32
#define DPAIR 64
#define NCOL  (NLOC * DPAIR)   // 24576

// ---------------- scratch (static device globals; no allocations) ----------
__device__ float g_At[DHID * NLOC];   // a transposed: [32][384]
__device__ float g_B [NLOC * DHID];   // b:            [384][32]
__device__ float g_C [DHID * NCOL];   // C[x][j*64+p]: [32][24576]  (3 MB)

// ---------------- f32x2 helpers (Blackwell packed fp32) --------------------
__device__ __forceinline__ unsigned long long dup2(float v) {
    unsigned long long r;
    asm("mov.b64 %0, {%1, %1};" : "=l"(r) : "f"(v));
    return r;
}
__device__ __forceinline__ void fma2(unsigned long long& d,
                                     unsigned long long a,
                                     unsigned long long b) {
    asm("fma.rn.f32x2 %0, %1, %2, %0;" : "+l"(d) : "l"(a), "l"(b));
}
__device__ __forceinline__ float2 unpk(unsigned long long u) {
    float2 r;
    asm("mov.b64 {%0, %1}, %2;" : "=f"(r.x), "=f"(r.y) : "l"(u));
    return r;
}

// ---------------- kernel 1: ab = m @ W_in^T + b_in, * op_mask --------------
// grid 96 x 256 threads; block handles 4 rows of m. float4 everywhere,
// 2 independent accumulators to break the FFMA dependency chain.
__global__ __launch_bounds__(256) void k1_proj(
        const float* __restrict__ m,
        const float* __restrict__ W_in,
        const float* __restrict__ b_in,
        const float* __restrict__ op_mask)
{
    __shared__ float W_s[64 * 132];       // row stride 132 floats (16B-aligned, pad 4)
    __shared__ float4 m4[4 * 32];
    const int tid = threadIdx.x;
    const int n0  = blockIdx.x * 4;

    const float4* Wg = (const float4*)W_in;   // [64][32] float4, row-major
    #pragma unroll
    for (int i = 0; i < 8; ++i) {
        int e = tid + i * 256;                // 0..2047
        int h = e >> 5, kq = e & 31;
        ((float4*)(W_s + h * 132))[kq] = Wg[e];
    }
    if (tid < 128) m4[tid] = ((const float4*)m)[(size_t)n0 * 32 + tid];
    __syncthreads();

    const int nl = tid >> 6;                  // 0..3
    const int h  = tid & 63;                  // 0..63
    const float4* Wrow = (const float4*)(W_s + h * 132);
    const float4* mrow = &m4[nl * 32];

    float4 a0 = make_float4(0.f, 0.f, 0.f, 0.f);
    float4 a1 = make_float4(0.f, 0.f, 0.f, 0.f);
    #pragma unroll
    for (int kq = 0; kq < 32; kq += 2) {
        float4 w0 = Wrow[kq],     mv0 = mrow[kq];
        float4 w1 = Wrow[kq + 1], mv1 = mrow[kq + 1];
        a0.x += mv0.x * w0.x; a0.y += mv0.y * w0.y;
        a0.z += mv0.z * w0.z; a0.w += mv0.w * w0.w;
        a1.x += mv1.x * w1.x; a1.y += mv1.y * w1.y;
        a1.z += mv1.z * w1.z; a1.w += mv1.w * w1.w;
    }
    float acc = (a0.x + a0.y) + (a0.z + a0.w) + (a1.x + a1.y) + (a1.z + a1.w);
    acc = (acc + b_in[h]) * op_mask[0];

    const int n = n0 + nl;
    if (h < DHID) g_At[h * NLOC + n]          = acc;   // a, transposed
    else          g_B [n * DHID + (h - DHID)] = acc;   // b
}

// ---------------- kernel 2: C[x][j*64+p] = sum_y b[j,y]*W_out[p,32x+y] -----
// grid (32 x-slices, 6 j-tiles of 64) x 256 threads, 4x4 register tile.
__global__ __launch_bounds__(256) void k2_makeC(const float* __restrict__ W_out)
{
    __shared__ float W_sT[32 * 68];   // [y][p], padded stride 68
    __shared__ float b_sT[32 * 68];   // [y][j], padded stride 68
    const int tid = threadIdx.x;
    const int x   = blockIdx.x;           // 0..31
    const int j0  = blockIdx.y * 64;      // 0..320

    #pragma unroll
    for (int i = 0; i < 8; ++i) {
        int e = tid + i * 256;             // 0..2047
        int p = e >> 5, y = e & 31;        // p doubles as local j index
        W_sT[y * 68 + p] = W_out[p * 1024 + x * 32 + y];
        b_sT[y * 68 + p] = g_B[(j0 + p) * DHID + y];
    }
    __syncthreads();

    const int jl = (tid >> 4) * 4;
    const int pl = (tid & 15) * 4;
    float acc[4][4] = {};
    #pragma unroll
    for (int y = 0; y < 32; ++y) {
        float4 bq = *(const float4*)&b_sT[y * 68 + jl];
        float4 wq = *(const float4*)&W_sT[y * 68 + pl];
        const float* bb = &bq.x;
        const float* ww = &wq.x;
        #pragma unroll
        for (int r = 0; r < 4; ++r)
            #pragma unroll
            for (int c = 0; c < 4; ++c)
                acc[r][c] += bb[r] * ww[c];
    }
    #pragma unroll
    for (int r = 0; r < 4; ++r) {
        float4 o = make_float4(acc[r][0], acc[r][1], acc[r][2], acc[r][3]);
        *(float4*)&g_C[x * NCOL + (j0 + jl + r) * 64 + pl] = o;
    }
}

// ---------------- kernel 3: Z[i,n] = sum_x a[i,x] * C[x,n] -----------------
// GEMM M=384, N=24576, K=32. BM=BN=128, 256 threads, 8x8 per thread.
// a stored PLAIN in smem (16 KB) and duplicated into f32x2 pairs in
// registers (ALU pipe is idle); c pairs come straight from smem.
__global__ __launch_bounds__(256) void k3_gemm(
        const float* __restrict__ b_out,
        const float* __restrict__ op_norm,
        float* __restrict__ out)
{
    __shared__ float a_s[32 * 128];   // [k][m]  16 KB
    __shared__ float c_s[32 * 128];   // [k][n]  16 KB
    const int tid = threadIdx.x;
    const int n0  = blockIdx.x * 128;
    const int m0  = blockIdx.y * 128;

    #pragma unroll
    for (int i = 0; i < 16; ++i) {
        int e = tid + i * 256;              // 0..4095
        int k = e >> 7, mm = e & 127;
        a_s[k * 128 + mm] = g_At[k * NLOC + m0 + mm];   // coalesced (At)
        c_s[k * 128 + mm] = g_C [k * NCOL + n0 + mm];   // coalesced
    }
    __syncthreads();

    const int tm = (tid >> 4) * 8;          // 0..120
    const int tn = (tid & 15) * 8;          // 0..120
    unsigned long long acc[8][4];
    #pragma unroll
    for (int mi = 0; mi < 8; ++mi)
        #pragma unroll
        for (int q = 0; q < 4; ++q)
            acc[mi][q] = 0ULL;              // bits of (0.f, 0.f)

    #pragma unroll 4
    for (int k = 0; k < 32; ++k) {
        float4 af0 = *(const float4*)&a_s[k * 128 + tm];
        float4 af1 = *(const float4*)&a_s[k * 128 + tm + 4];
        const float* cp = &c_s[k * 128 + tn];
        ulonglong2 b01 = *(const ulonglong2*)(cp);       // (c0,c1),(c2,c3)
        ulonglong2 b23 = *(const ulonglong2*)(cp + 4);   // (c4,c5),(c6,c7)

        unsigned long long av[8];
        av[0] = dup2(af0.x); av[1] = dup2(af0.y);
        av[2] = dup2(af0.z); av[3] = dup2(af0.w);
        av[4] = dup2(af1.x); av[5] = dup2(af1.y);
        av[6] = dup2(af1.z); av[7] = dup2(af1.w);
        unsigned long long bv[4] = {b01.x, b01.y, b23.x, b23.y};
        #pragma unroll
        for (int mi = 0; mi < 8; ++mi)
            #pragma unroll
            for (int q = 0; q < 4; ++q)
                fma2(acc[mi][q], av[mi], bv[q]);
    }

    const float opn = op_norm[0];
    float bo[8];
    #pragma unroll
    for (int l = 0; l < 8; ++l) bo[l] = b_out[(tn + l) & 63];  // n0%64==0

    #pragma unroll
    for (int mi = 0; mi < 8; ++mi) {
        float2 t0 = unpk(acc[mi][0]);
        float2 t1 = unpk(acc[mi][1]);
        float2 t2 = unpk(acc[mi][2]);
        float2 t3 = unpk(acc[mi][3]);
        float4 r0 = make_float4((t0.x + bo[0]) * opn, (t0.y + bo[1]) * opn,
                                (t1.x + bo[2]) * opn, (t1.y + bo[3]) * opn);
        float4 r1 = make_float4((t2.x + bo[4]) * opn, (t2.y + bo[5]) * opn,
                                (t3.x + bo[6]) * opn, (t3.y + bo[7]) * opn);
        int row = (m0 + tm + mi) * NCOL + n0 + tn;
        *(float4*)&out[row]     = r0;
        *(float4*)&out[row + 4] = r1;
    }
}

// ---------------- launch ---------------------------------------------------
extern "C" void kernel_launch(void* const* d_in, const int* in_sizes, int n_in,
                              void* d_out, int out_size)
{
    (void)in_sizes; (void)n_in; (void)out_size;
    const float* m       = (const float*)d_in[0];
    /* d_in[1] = nlist: unused by the reference */
    const float* op_mask = (const float*)d_in[2];
    const float* op_norm = (const float*)d_in[3];
    const float* W_in    = (const float*)d_in[4];
    const float* b_in    = (const float*)d_in[5];
    const float* W_out   = (const float*)d_in[6];
    const float* b_out   = (const float*)d_in[7];
    float* out = (float*)d_out;

    k1_proj <<<96, 256>>>(m, W_in, b_in, op_mask);
    k2_makeC<<<dim3(32, 6), 256>>>(W_out);
    k3_gemm <<<dim3(192, 3), 256>>>(b_out, op_norm, out);
}

// round 4
// speedup vs baseline: 1.2485x; 1.1825x over previous
#include <cuda_runtime.h>
#include <cuda_bf16.h>
#include <cstdint>

#define NLOC  384
#define DHID  32
#define DPAIR 64
#define NCOL  (NLOC * DPAIR)   // 24576

// ---------------- scratch (static device globals; no allocations) ----------
__device__ float g_B[NLOC * DHID];                         // b fp32 [384][32]
__device__ __align__(16) __nv_bfloat16 g_Ah[NLOC * DHID];  // a hi  [384][32]
__device__ __align__(16) __nv_bfloat16 g_Al[NLOC * DHID];  // a lo  [384][32]
__device__ __align__(16) __nv_bfloat16 g_Ch[NCOL * DHID];  // C hi  [24576][32]
__device__ __align__(16) __nv_bfloat16 g_Cl[NCOL * DHID];  // C lo  [24576][32]

// ---------------- mma.sync / ldmatrix helpers (compute_80+, OK on 103) -----
__device__ __forceinline__ uint32_t smem_u32(const void* p) {
    uint32_t a;
    asm("{ .reg .u64 t; cvta.to.shared.u64 t, %1; cvt.u32.u64 %0, t; }"
        : "=r"(a) : "l"(p));
    return a;
}
__device__ __forceinline__ void ldsm_x4(uint32_t* r, uint32_t addr) {
    asm volatile("ldmatrix.sync.aligned.m8n8.x4.shared.b16 {%0,%1,%2,%3}, [%4];"
                 : "=r"(r[0]), "=r"(r[1]), "=r"(r[2]), "=r"(r[3]) : "r"(addr));
}
__device__ __forceinline__ void ldsm_x2(uint32_t* r, uint32_t addr) {
    asm volatile("ldmatrix.sync.aligned.m8n8.x2.shared.b16 {%0,%1}, [%2];"
                 : "=r"(r[0]), "=r"(r[1]) : "r"(addr));
}
__device__ __forceinline__ void mma_bf16(float* d, const uint32_t* a,
                                         const uint32_t* b) {
    asm volatile(
        "mma.sync.aligned.m16n8k16.row.col.f32.bf16.bf16.f32 "
        "{%0,%1,%2,%3}, {%4,%5,%6,%7}, {%8,%9}, {%0,%1,%2,%3};"
        : "+f"(d[0]), "+f"(d[1]), "+f"(d[2]), "+f"(d[3])
        : "r"(a[0]), "r"(a[1]), "r"(a[2]), "r"(a[3]), "r"(b[0]), "r"(b[1]));
}

// ---------------- kernel 1: ab = m @ W_in^T + b_in, * op_mask --------------
// grid 384 (1 block per row n), 256 threads = 64 h x 4 k-chunks.
__global__ __launch_bounds__(256) void k1_proj(
        const float* __restrict__ m,
        const float* __restrict__ W_in,
        const float* __restrict__ b_in,
        const float* __restrict__ op_mask)
{
    __shared__ float red[256];
    const int tid = threadIdx.x;
    const int n   = blockIdx.x;
    const int kc  = tid >> 6;          // 0..3
    const int h   = tid & 63;          // 0..63

    const float4* mg = (const float4*)m    + (size_t)n * 32 + kc * 8;
    const float4* wg = (const float4*)W_in + (size_t)h * 32 + kc * 8;

    float4 acc0 = make_float4(0.f, 0.f, 0.f, 0.f);
    float4 acc1 = make_float4(0.f, 0.f, 0.f, 0.f);
    #pragma unroll
    for (int i = 0; i < 8; i += 2) {
        float4 mv0 = mg[i],     wv0 = wg[i];
        float4 mv1 = mg[i + 1], wv1 = wg[i + 1];
        acc0.x += mv0.x * wv0.x; acc0.y += mv0.y * wv0.y;
        acc0.z += mv0.z * wv0.z; acc0.w += mv0.w * wv0.w;
        acc1.x += mv1.x * wv1.x; acc1.y += mv1.y * wv1.y;
        acc1.z += mv1.z * wv1.z; acc1.w += mv1.w * wv1.w;
    }
    red[tid] = (acc0.x + acc0.y) + (acc0.z + acc0.w)
             + (acc1.x + acc1.y) + (acc1.z + acc1.w);
    __syncthreads();

    if (tid < 64) {
        float acc = red[tid] + red[tid + 64] + red[tid + 128] + red[tid + 192];
        acc = (acc + b_in[tid]) * op_mask[0];
        if (tid < DHID) {
            __nv_bfloat16 ah = __float2bfloat16(acc);
            __nv_bfloat16 al = __float2bfloat16(acc - __bfloat162float(ah));
            g_Ah[n * DHID + tid] = ah;
            g_Al[n * DHID + tid] = al;
        } else {
            g_B[n * DHID + (tid - DHID)] = acc;
        }
    }
}

// ---------------- kernel 2: C[n=j*64+p][x] = sum_y b[j,y]*W_out[p,32x+y] ---
// Output split to bf16 hi/lo in B-operand ([N][K] K-major) layout.
__global__ __launch_bounds__(256) void k2_makeC(const float* __restrict__ W_out)
{
    __shared__ float W_t[256 * 33];
    __shared__ float b_s[16 * 32];
    const int tid = threadIdx.x;
    const int rt  = blockIdx.x;          // rows rt*256..+255 (row = p*32+x)
    const int j0  = blockIdx.y * 16;

    #pragma unroll
    for (int i = 0; i < 32; ++i) {
        int e = tid + i * 256;
        int row = e >> 5, y = e & 31;
        W_t[row * 33 + y] = W_out[rt * 8192 + e];
    }
    #pragma unroll
    for (int i = 0; i < 2; ++i) {
        int e = tid + i * 256;
        if (e < 512) b_s[e] = g_B[(j0 + (e >> 5)) * DHID + (e & 31)];
    }
    __syncthreads();

    float wreg[32];
    #pragma unroll
    for (int y = 0; y < 32; ++y) wreg[y] = W_t[tid * 33 + y];

    float acc[16];
    #pragma unroll
    for (int j = 0; j < 16; ++j) acc[j] = 0.f;
    #pragma unroll
    for (int y = 0; y < 32; ++y) {
        float w = wreg[y];
        #pragma unroll
        for (int j = 0; j < 16; ++j) acc[j] += w * b_s[j * 32 + y];
    }

    const int row = rt * 256 + tid;      // row = p*32 + x
    #pragma unroll
    for (int j = 0; j < 16; ++j) {
        float c = acc[j];
        __nv_bfloat16 ch = __float2bfloat16(c);
        __nv_bfloat16 cl = __float2bfloat16(c - __bfloat162float(ch));
        int idx = (j0 + j) * 2048 + row; // = n*32 + x
        g_Ch[idx] = ch;
        g_Cl[idx] = cl;
    }
}

// ---------------- kernel 3: Z = A @ C^T via mma.sync bf16, 3-pass split ----
// Block: M=128, N=128, K=32. 8 warps as 4(M) x 2(N).
// smem rows padded to 40 bf16 (80B) -> ldmatrix conflict-free.
#define SROW 40
__global__ __launch_bounds__(256) void k3_gemm_mma(
        const float* __restrict__ b_out,
        const float* __restrict__ op_norm,
        float* __restrict__ out)
{
    __shared__ __align__(16) __nv_bfloat16 sAh[128 * SROW];
    __shared__ __align__(16) __nv_bfloat16 sAl[128 * SROW];
    __shared__ __align__(16) __nv_bfloat16 sBh[128 * SROW];
    __shared__ __align__(16) __nv_bfloat16 sBl[128 * SROW];
    __shared__ float s_bias[64];

    const int tid  = threadIdx.x;
    const int wid  = tid >> 5;
    const int lane = tid & 31;
    const int n0   = blockIdx.x * 128;
    const int m0   = blockIdx.y * 128;

    // ---- global -> smem (16B chunks, coalesced) ----
    #pragma unroll
    for (int i = 0; i < 2; ++i) {
        int e = tid + i * 256;            // 0..511
        int row = e >> 2, ch = e & 3;
        size_t ga = (size_t)(m0 + row) * DHID + ch * 8;
        size_t gb = (size_t)(n0 + row) * DHID + ch * 8;
        int d = row * SROW + ch * 8;
        *(uint4*)(sAh + d) = *(const uint4*)(g_Ah + ga);
        *(uint4*)(sAl + d) = *(const uint4*)(g_Al + ga);
        *(uint4*)(sBh + d) = *(const uint4*)(g_Ch + gb);
        *(uint4*)(sBl + d) = *(const uint4*)(g_Cl + gb);
    }
    if (tid < 64) s_bias[tid] = b_out[tid];
    __syncthreads();

    const int warp_m = wid & 3;           // 32 rows each
    const int warp_n = wid >> 2;          // 64 cols each

    const uint32_t ah_b = smem_u32(sAh);
    const uint32_t al_b = smem_u32(sAl);
    const uint32_t bh_b = smem_u32(sBh);
    const uint32_t bl_b = smem_u32(sBl);

    float D[2][8][4];
    #pragma unroll
    for (int mf = 0; mf < 2; ++mf)
        #pragma unroll
        for (int nf = 0; nf < 8; ++nf)
            #pragma unroll
            for (int q = 0; q < 4; ++q) D[mf][nf][q] = 0.f;

    #pragma unroll
    for (int ks = 0; ks < 2; ++ks) {
        const int kk = ks * 16;
        uint32_t Ah[2][4], Al[2][4];
        #pragma unroll
        for (int mf = 0; mf < 2; ++mf) {
            int row = warp_m * 32 + mf * 16 + (lane & 15);
            int col = kk + (lane >> 4) * 8;
            uint32_t off = row * (SROW * 2) + col * 2;
            ldsm_x4(Ah[mf], ah_b + off);
            ldsm_x4(Al[mf], al_b + off);
        }
        int brow = warp_n * 64 + (lane & 7);
        int bcol = kk + (lane & 8);
        uint32_t boff = brow * (SROW * 2) + bcol * 2;
        #pragma unroll
        for (int nf = 0; nf < 8; ++nf) {
            uint32_t Bh[2], Bl[2];
            ldsm_x2(Bh, bh_b + boff);
            ldsm_x2(Bl, bl_b + boff);
            boff += 8 * (SROW * 2);
            #pragma unroll
            for (int mf = 0; mf < 2; ++mf) {
                mma_bf16(D[mf][nf], Ah[mf], Bh);
                mma_bf16(D[mf][nf], Ah[mf], Bl);
                mma_bf16(D[mf][nf], Al[mf], Bh);
            }
        }
    }

    // ---- epilogue ----
    const float opn = op_norm[0];
    const int rgrp  = lane >> 2;
    const int cpair = (lane & 3) * 2;
    #pragma unroll
    for (int mf = 0; mf < 2; ++mf) {
        #pragma unroll
        for (int nf = 0; nf < 8; ++nf) {
            int col  = n0 + warp_n * 64 + nf * 8 + cpair;
            float b0 = s_bias[nf * 8 + cpair];
            float b1 = s_bias[nf * 8 + cpair + 1];
            int r0 = m0 + warp_m * 32 + mf * 16 + rgrp;
            float2 v0 = make_float2((D[mf][nf][0] + b0) * opn,
                                    (D[mf][nf][1] + b1) * opn);
            float2 v1 = make_float2((D[mf][nf][2] + b0) * opn,
                                    (D[mf][nf][3] + b1) * opn);
            *(float2*)(out + (size_t)r0 * NCOL + col)       = v0;
            *(float2*)(out + (size_t)(r0 + 8) * NCOL + col) = v1;
        }
    }
}

// ---------------- launch ---------------------------------------------------
extern "C" void kernel_launch(void* const* d_in, const int* in_sizes, int n_in,
                              void* d_out, int out_size)
{
    (void)in_sizes; (void)n_in; (void)out_size;
    const float* m       = (const float*)d_in[0];
    /* d_in[1] = nlist: unused by the reference */
    const float* op_mask = (const float*)d_in[2];
    const float* op_norm = (const float*)d_in[3];
    const float* W_in    = (const float*)d_in[4];
    const float* b_in    = (const float*)d_in[5];
    const float* W_out   = (const float*)d_in[6];
    const float* b_out   = (const float*)d_in[7];
    float* out = (float*)d_out;

    k1_proj    <<<384, 256>>>(m, W_in, b_in, op_mask);
    k2_makeC   <<<dim3(8, 24), 256>>>(W_out);
    k3_gemm_mma<<<dim3(192, 3), 256>>>(b_out, op_norm, out);
}